// round 5
// baseline (speedup 1.0000x reference)
#include <cuda_runtime.h>
#include <cstdio>

#define MAXN 500000
#define MAXE 1000000
#define NB_MAX 512
#define SCAN_T 1024
#define SCAN_TILE 2048

// ---------------- scratch (device globals; no allocations) ----------------
__device__ int g_deg[MAXN];
__device__ int g_rowptr[MAXN + 1];
__device__ int g_cursor[MAXN];
__device__ int g_adj[MAXE];
__device__ int g_bsums[NB_MAX];
__device__ float g_h1[MAXN * 32];
__device__ float g_h2[MAXN * 64];
__device__ float g_h3[MAXN * 64];

// ---------------- helpers ----------------
__device__ __forceinline__ float2 ffma2(float a, float2 b, float2 c) {
    unsigned long long av, bv, cv, dv;
    unsigned int au = __float_as_uint(a);
    asm("mov.b64 %0, {%1, %1};" : "=l"(av) : "r"(au));
    bv = *reinterpret_cast<unsigned long long*>(&b);
    cv = *reinterpret_cast<unsigned long long*>(&c);
    asm("fma.rn.f32x2 %0, %1, %2, %3;" : "=l"(dv) : "l"(av), "l"(bv), "l"(cv));
    return *reinterpret_cast<float2*>(&dv);
}

// ---------------- CSR build ----------------
__global__ void k_zero_deg(int n) {
    int t = blockIdx.x * blockDim.x + threadIdx.x;
    if (t < n) g_deg[t] = 0;
}

__global__ void k_count_deg(const int* __restrict__ ei, int nE) {
    int e = blockIdx.x * blockDim.x + threadIdx.x;
    if (e >= nE) return;
    atomicAdd(&g_deg[ei[nE + e]], 1);
}

__global__ void k_scan_reduce(int n) {
    __shared__ int sd[SCAN_T];
    int base = blockIdx.x * SCAN_TILE + threadIdx.x * 2;
    int s = 0;
    if (base < n) s += g_deg[base];
    if (base + 1 < n) s += g_deg[base + 1];
    sd[threadIdx.x] = s;
    __syncthreads();
    for (int d = SCAN_T / 2; d > 0; d >>= 1) {
        if (threadIdx.x < d) sd[threadIdx.x] += sd[threadIdx.x + d];
        __syncthreads();
    }
    if (threadIdx.x == 0) g_bsums[blockIdx.x] = sd[0];
}

// parallel exclusive scan over block sums (nb <= NB_MAX)
__global__ void k_scan_mid(int nb, int nN) {
    __shared__ int sd[NB_MAX];
    int tid = threadIdx.x;
    int v0 = (tid < nb) ? g_bsums[tid] : 0;
    sd[tid] = v0;
    __syncthreads();
    for (int d = 1; d < NB_MAX; d <<= 1) {
        int v = (tid >= d) ? sd[tid - d] : 0;
        __syncthreads();
        sd[tid] += v;
        __syncthreads();
    }
    if (tid < nb) g_bsums[tid] = sd[tid] - v0;
    if (tid == NB_MAX - 1) g_rowptr[nN] = sd[NB_MAX - 1];
}

__global__ void k_scan_final(int n) {
    __shared__ int sd[SCAN_T];
    int tid = threadIdx.x;
    int base = blockIdx.x * SCAN_TILE + tid * 2;
    int t0 = (base < n) ? g_deg[base] : 0;
    int t1 = (base + 1 < n) ? g_deg[base + 1] : 0;
    int ts = t0 + t1;
    sd[tid] = ts;
    __syncthreads();
    for (int d = 1; d < SCAN_T; d <<= 1) {
        int v = (tid >= d) ? sd[tid - d] : 0;
        __syncthreads();
        sd[tid] += v;
        __syncthreads();
    }
    int excl = sd[tid] - ts + g_bsums[blockIdx.x];
    if (base < n)     { g_rowptr[base]     = excl;      g_cursor[base]     = excl; }
    if (base + 1 < n) { g_rowptr[base + 1] = excl + t0; g_cursor[base + 1] = excl + t0; }
}

__global__ void k_fill_adj(const int* __restrict__ ei, const int* __restrict__ et, int nE) {
    int e = blockIdx.x * blockDim.x + threadIdx.x;
    if (e >= nE) return;
    int src = ei[e];
    int dst = ei[nE + e];
    int r = et[e];
    int pos = atomicAdd(&g_cursor[dst], 1);
    g_adj[pos] = (src << 2) | r;
}

// ---------------- pre-MLP ----------------
__global__ void k_pre(const int* __restrict__ x,
                      const float* __restrict__ shape_emb,
                      const float* __restrict__ color_emb,
                      const float* __restrict__ pre_w,
                      const float* __restrict__ pre_b,
                      int n) {
    int t = blockIdx.x * blockDim.x + threadIdx.x;
    if (t >= n * 32) return;
    int node = t >> 5;
    int f = t & 31;
    int si = __ldg(&x[2 * node]);
    int ci = __ldg(&x[2 * node + 1]);
    float s = __ldg(&pre_b[f]);
#pragma unroll
    for (int k = 0; k < 8; k++)
        s += __ldg(&shape_emb[si * 8 + k]) * __ldg(&pre_w[k * 32 + f]);
#pragma unroll
    for (int k = 0; k < 8; k++)
        s += __ldg(&color_emb[ci * 8 + k]) * __ldg(&pre_w[(8 + k) * 32 + f]);
    g_h1[node * 32 + f] = fmaxf(s, 0.f);
}

// ---------------- fused RGCN layer: agg into SMEM + GEMM from SMEM ----------------
// Block owns 64 nodes. Phase 1: each warp aggregates its 8 nodes' relation means
// + own features directly into the SMEM A-tile [64][4F]. Phase 2: register-blocked
// GEMM C[64,64] = relu(A @ [w_rel;w_root] + b) with f32x2 packed FMA.
template <int F>
__global__ void __launch_bounds__(256)
k_layer_fused(const float* __restrict__ h_in,
              const float* __restrict__ w_rel,   // [3, F, 64]
              const float* __restrict__ w_root,  // [F, 64]
              const float* __restrict__ bias,    // [64]
              float* __restrict__ h_out, int n) {
    constexpr int K = 4 * F;
    constexpr int R = F / 32;
    constexpr int AP = K + 4;

    extern __shared__ float sm[];
    float* W_sm = sm;              // [K][64]
    float* A_sm = sm + K * 64;     // [64][AP]

    // stage weights (L2-resident across blocks)
    {
        const float4* wr4 = (const float4*)w_rel;
        const float4* wo4 = (const float4*)w_root;
        constexpr int NREL4 = 3 * F * 64 / 4;
        constexpr int NW4 = K * 64 / 4;
        float4* W4 = (float4*)W_sm;
        for (int i = threadIdx.x; i < NW4; i += 256)
            W4[i] = (i < NREL4) ? __ldg(&wr4[i]) : __ldg(&wo4[i - NREL4]);
    }

    const int lane = threadIdx.x & 31;
    const int warp = threadIdx.x >> 5;
    const int base = blockIdx.x * 64;

    // ---- phase 1: aggregation into A_sm ----
#pragma unroll 1
    for (int i = 0; i < 8; i++) {
        const int nl = warp * 8 + i;
        const int node = base + nl;
        float* row = A_sm + nl * AP;
        if (node < n) {
            float hh[R], a0[R], a1[R], a2[R];
#pragma unroll
            for (int j = 0; j < R; j++) {
                a0[j] = 0.f; a1[j] = 0.f; a2[j] = 0.f;
                hh[j] = __ldg(&h_in[(size_t)node * F + 32 * j + lane]);
            }
            int c0 = 0, c1 = 0, c2 = 0;
            int rs = __ldg(&g_rowptr[node]);
            int re = __ldg(&g_rowptr[node + 1]);
            for (int e = rs; e < re; ++e) {
                int p = __ldg(&g_adj[e]);
                int src = p >> 2;
                int r = p & 3;
                float v[R];
#pragma unroll
                for (int j = 0; j < R; j++) v[j] = __ldg(&h_in[(size_t)src * F + 32 * j + lane]);
                if (r == 0) { c0++;
#pragma unroll
                    for (int j = 0; j < R; j++) a0[j] += v[j];
                } else if (r == 1) { c1++;
#pragma unroll
                    for (int j = 0; j < R; j++) a1[j] += v[j];
                } else { c2++;
#pragma unroll
                    for (int j = 0; j < R; j++) a2[j] += v[j];
                }
            }
            float s0 = 1.f / (float)((c0 > 1) ? c0 : 1);
            float s1 = 1.f / (float)((c1 > 1) ? c1 : 1);
            float s2 = 1.f / (float)((c2 > 1) ? c2 : 1);
#pragma unroll
            for (int j = 0; j < R; j++) {
                row[0 * F + 32 * j + lane] = a0[j] * s0;
                row[1 * F + 32 * j + lane] = a1[j] * s1;
                row[2 * F + 32 * j + lane] = a2[j] * s2;
                row[3 * F + 32 * j + lane] = hh[j];
            }
        } else {
#pragma unroll
            for (int j = 0; j < 4 * R; j++) row[32 * j + lane] = 0.f;
        }
    }
    __syncthreads();

    // ---- phase 2: GEMM ----
    const float2 bb = *(const float2*)&bias[2 * lane];
    float2 acc[8];
#pragma unroll
    for (int i = 0; i < 8; i++) acc[i] = make_float2(0.f, 0.f);

    const float* Ab = A_sm + (warp * 8) * AP;
#pragma unroll 4
    for (int k4 = 0; k4 < K / 4; k4++) {
        float2 w0 = *(const float2*)&W_sm[(4 * k4 + 0) * 64 + 2 * lane];
        float2 w1 = *(const float2*)&W_sm[(4 * k4 + 1) * 64 + 2 * lane];
        float2 w2 = *(const float2*)&W_sm[(4 * k4 + 2) * 64 + 2 * lane];
        float2 w3 = *(const float2*)&W_sm[(4 * k4 + 3) * 64 + 2 * lane];
#pragma unroll
        for (int i = 0; i < 8; i++) {
            float4 a = *(const float4*)&Ab[i * AP + 4 * k4];
            acc[i] = ffma2(a.x, w0, acc[i]);
            acc[i] = ffma2(a.y, w1, acc[i]);
            acc[i] = ffma2(a.z, w2, acc[i]);
            acc[i] = ffma2(a.w, w3, acc[i]);
        }
    }
#pragma unroll
    for (int i = 0; i < 8; i++) {
        int node = base + warp * 8 + i;
        if (node < n) {
            float2 r;
            r.x = fmaxf(acc[i].x + bb.x, 0.f);
            r.y = fmaxf(acc[i].y + bb.y, 0.f);
            *(float2*)&h_out[(size_t)node * 64 + 2 * lane] = r;
        }
    }
}

// ---------------- classifier ----------------
__global__ void k_cls(const int* __restrict__ ptr,
                      const float* __restrict__ cls_w,
                      const float* __restrict__ cls_b,
                      float* __restrict__ out,
                      int nG) {
    int t = blockIdx.x * blockDim.x + threadIdx.x;
    if (t >= nG * 10) return;
    int g = t / 10;
    int c = t % 10;
    int idx = __ldg(&ptr[g + 1]) - 1;
    const float* hrow = &g_h3[(size_t)idx * 64];
    float s = __ldg(&cls_b[c]);
#pragma unroll
    for (int k = 0; k < 64; k++) s += hrow[k] * __ldg(&cls_w[k * 10 + c]);
    out[t] = s;
}

// ---------------- launch ----------------
extern "C" void kernel_launch(void* const* d_in, const int* in_sizes, int n_in,
                              void* d_out, int out_size) {
    const int* x          = (const int*)d_in[0];
    const int* edge_index = (const int*)d_in[1];
    const int* edge_type  = (const int*)d_in[2];
    const int* ptr        = (const int*)d_in[3];
    const float* shape_emb = (const float*)d_in[4];
    const float* color_emb = (const float*)d_in[5];
    const float* pre_w    = (const float*)d_in[6];
    const float* pre_b    = (const float*)d_in[7];
    const float* w1_rel   = (const float*)d_in[8];
    const float* w1_root  = (const float*)d_in[9];
    const float* b1       = (const float*)d_in[10];
    const float* w2_rel   = (const float*)d_in[11];
    const float* w2_root  = (const float*)d_in[12];
    const float* b2       = (const float*)d_in[13];
    const float* cls_w    = (const float*)d_in[14];
    const float* cls_b    = (const float*)d_in[15];
    float* out = (float*)d_out;

    const int nN = in_sizes[0] / 2;
    const int nE = in_sizes[2];
    const int nG = in_sizes[3] - 1;
    const int nb = (nN + SCAN_TILE - 1) / SCAN_TILE;

    float *h1, *h2, *h3;
    cudaGetSymbolAddress((void**)&h1, g_h1);
    cudaGetSymbolAddress((void**)&h2, g_h2);
    cudaGetSymbolAddress((void**)&h3, g_h3);

    const int smem_l1 = (128 * 64 + 64 * 132) * (int)sizeof(float);   // ~66.6 KB
    const int smem_l2 = (256 * 64 + 64 * 260) * (int)sizeof(float);   // ~132.1 KB
    cudaFuncSetAttribute(k_layer_fused<32>, cudaFuncAttributeMaxDynamicSharedMemorySize, smem_l1);
    cudaFuncSetAttribute(k_layer_fused<64>, cudaFuncAttributeMaxDynamicSharedMemorySize, smem_l2);

    // CSR by destination
    k_zero_deg<<<(nN + 255) / 256, 256>>>(nN);
    k_count_deg<<<(nE + 255) / 256, 256>>>(edge_index, nE);
    k_scan_reduce<<<nb, SCAN_T>>>(nN);
    k_scan_mid<<<1, NB_MAX>>>(nb, nN);
    k_scan_final<<<nb, SCAN_T>>>(nN);
    k_fill_adj<<<(nE + 255) / 256, 256>>>(edge_index, edge_type, nE);

    // Feature pipeline
    k_pre<<<(nN * 32 + 255) / 256, 256>>>(x, shape_emb, color_emb, pre_w, pre_b, nN);

    const int nblk = (nN + 63) / 64;
    k_layer_fused<32><<<nblk, 256, smem_l1>>>(h1, w1_rel, w1_root, b1, h2, nN);
    k_layer_fused<64><<<nblk, 256, smem_l2>>>(h2, w2_rel, w2_root, b2, h3, nN);

    k_cls<<<(nG * 10 + 255) / 256, 256>>>(ptr, cls_w, cls_b, out, nG);
}

// round 6
// speedup vs baseline: 1.5395x; 1.5395x over previous
#include <cuda_runtime.h>
#include <cstdio>

#define MAXN 500000
#define MAXE 1000000
#define NB_MAX 512
#define SCAN_T 1024
#define SCAN_TILE 2048
#define NSM 152

// ---------------- scratch (device globals; no allocations) ----------------
__device__ int g_deg[MAXN];
__device__ int g_rowptr[MAXN + 1];
__device__ int g_cursor[MAXN];
__device__ int g_adj[MAXE];
__device__ int g_bsums[NB_MAX];
__device__ float g_h1[MAXN * 32];
__device__ float g_h2[MAXN * 64];
__device__ float g_h3[MAXN * 64];
__device__ float g_cat[(size_t)MAXN * 256];

// ---------------- helpers ----------------
__device__ __forceinline__ float2 ffma2(float a, float2 b, float2 c) {
    unsigned long long av, bv, cv, dv;
    unsigned int au = __float_as_uint(a);
    asm("mov.b64 %0, {%1, %1};" : "=l"(av) : "r"(au));
    bv = *reinterpret_cast<unsigned long long*>(&b);
    cv = *reinterpret_cast<unsigned long long*>(&c);
    asm("fma.rn.f32x2 %0, %1, %2, %3;" : "=l"(dv) : "l"(av), "l"(bv), "l"(cv));
    return *reinterpret_cast<float2*>(&dv);
}

__device__ __forceinline__ unsigned int smem_u32(const void* p) {
    return (unsigned int)__cvta_generic_to_shared(p);
}

#define CP_ASYNC16(dst, src) \
    asm volatile("cp.async.cg.shared.global [%0], [%1], 16;" :: "r"(dst), "l"(src))
#define CP_COMMIT() asm volatile("cp.async.commit_group;")
#define CP_WAIT0()  asm volatile("cp.async.wait_group 0;")

// ---------------- CSR build ----------------
__global__ void k_zero_deg(int n) {
    int t = blockIdx.x * blockDim.x + threadIdx.x;
    if (t < n) g_deg[t] = 0;
}

__global__ void k_count_deg(const int* __restrict__ ei, int nE) {
    int e = blockIdx.x * blockDim.x + threadIdx.x;
    if (e >= nE) return;
    atomicAdd(&g_deg[ei[nE + e]], 1);
}

__global__ void k_scan_reduce(int n) {
    __shared__ int sd[SCAN_T];
    int base = blockIdx.x * SCAN_TILE + threadIdx.x * 2;
    int s = 0;
    if (base < n) s += g_deg[base];
    if (base + 1 < n) s += g_deg[base + 1];
    sd[threadIdx.x] = s;
    __syncthreads();
    for (int d = SCAN_T / 2; d > 0; d >>= 1) {
        if (threadIdx.x < d) sd[threadIdx.x] += sd[threadIdx.x + d];
        __syncthreads();
    }
    if (threadIdx.x == 0) g_bsums[blockIdx.x] = sd[0];
}

// parallel exclusive scan over block sums (nb <= NB_MAX)
__global__ void k_scan_mid(int nb, int nN) {
    __shared__ int sd[NB_MAX];
    int tid = threadIdx.x;
    int v0 = (tid < nb) ? g_bsums[tid] : 0;
    sd[tid] = v0;
    __syncthreads();
    for (int d = 1; d < NB_MAX; d <<= 1) {
        int v = (tid >= d) ? sd[tid - d] : 0;
        __syncthreads();
        sd[tid] += v;
        __syncthreads();
    }
    if (tid < nb) g_bsums[tid] = sd[tid] - v0;
    if (tid == NB_MAX - 1) g_rowptr[nN] = sd[NB_MAX - 1];
}

__global__ void k_scan_final(int n) {
    __shared__ int sd[SCAN_T];
    int tid = threadIdx.x;
    int base = blockIdx.x * SCAN_TILE + tid * 2;
    int t0 = (base < n) ? g_deg[base] : 0;
    int t1 = (base + 1 < n) ? g_deg[base + 1] : 0;
    int ts = t0 + t1;
    sd[tid] = ts;
    __syncthreads();
    for (int d = 1; d < SCAN_T; d <<= 1) {
        int v = (tid >= d) ? sd[tid - d] : 0;
        __syncthreads();
        sd[tid] += v;
        __syncthreads();
    }
    int excl = sd[tid] - ts + g_bsums[blockIdx.x];
    if (base < n)     { g_rowptr[base]     = excl;      g_cursor[base]     = excl; }
    if (base + 1 < n) { g_rowptr[base + 1] = excl + t0; g_cursor[base + 1] = excl + t0; }
}

__global__ void k_fill_adj(const int* __restrict__ ei, const int* __restrict__ et, int nE) {
    int e = blockIdx.x * blockDim.x + threadIdx.x;
    if (e >= nE) return;
    int src = ei[e];
    int dst = ei[nE + e];
    int r = et[e];
    int pos = atomicAdd(&g_cursor[dst], 1);
    g_adj[pos] = (src << 2) | r;
}

// ---------------- pre-MLP ----------------
__global__ void k_pre(const int* __restrict__ x,
                      const float* __restrict__ shape_emb,
                      const float* __restrict__ color_emb,
                      const float* __restrict__ pre_w,
                      const float* __restrict__ pre_b,
                      int n) {
    int t = blockIdx.x * blockDim.x + threadIdx.x;
    if (t >= n * 32) return;
    int node = t >> 5;
    int f = t & 31;
    int si = __ldg(&x[2 * node]);
    int ci = __ldg(&x[2 * node + 1]);
    float s = __ldg(&pre_b[f]);
#pragma unroll
    for (int k = 0; k < 8; k++)
        s += __ldg(&shape_emb[si * 8 + k]) * __ldg(&pre_w[k * 32 + f]);
#pragma unroll
    for (int k = 0; k < 8; k++)
        s += __ldg(&color_emb[ci * 8 + k]) * __ldg(&pre_w[(8 + k) * 32 + f]);
    g_h1[node * 32 + f] = fmaxf(s, 0.f);
}

// ---------------- aggregation F=32: warp per node, scalar lanes ----------------
__global__ void __launch_bounds__(256)
k_agg32(const float* __restrict__ h_in, int n) {
    int node = blockIdx.x * 8 + (threadIdx.x >> 5);
    if (node >= n) return;
    const int lane = threadIdx.x & 31;

    float hh = __ldg(&h_in[(size_t)node * 32 + lane]);
    float a0 = 0.f, a1 = 0.f, a2 = 0.f;
    int c0 = 0, c1 = 0, c2 = 0;
    int rs = __ldg(&g_rowptr[node]);
    int re = __ldg(&g_rowptr[node + 1]);
    for (int e = rs; e < re; ++e) {
        int p = __ldg(&g_adj[e]);
        int src = p >> 2;
        int r = p & 3;
        float v = __ldg(&h_in[(size_t)src * 32 + lane]);
        if (r == 0)      { c0++; a0 += v; }
        else if (r == 1) { c1++; a1 += v; }
        else             { c2++; a2 += v; }
    }
    float s0 = 1.f / (float)((c0 > 1) ? c0 : 1);
    float s1 = 1.f / (float)((c1 > 1) ? c1 : 1);
    float s2 = 1.f / (float)((c2 > 1) ? c2 : 1);

    float* row = g_cat + (size_t)node * 128;
    row[lane]      = a0 * s0;
    row[32 + lane] = a1 * s1;
    row[64 + lane] = a2 * s2;
    row[96 + lane] = hh;
}

// ---------------- aggregation F=64: warp per node, float2 lanes ----------------
__global__ void __launch_bounds__(256)
k_agg64(const float* __restrict__ h_in, int n) {
    int node = blockIdx.x * 8 + (threadIdx.x >> 5);
    if (node >= n) return;
    const int lane = threadIdx.x & 31;

    float2 hh = *(const float2*)&h_in[(size_t)node * 64 + 2 * lane];
    float2 a0 = make_float2(0.f, 0.f), a1 = a0, a2 = a0;
    int c0 = 0, c1 = 0, c2 = 0;
    int rs = __ldg(&g_rowptr[node]);
    int re = __ldg(&g_rowptr[node + 1]);
    for (int e = rs; e < re; ++e) {
        int p = __ldg(&g_adj[e]);
        int src = p >> 2;
        int r = p & 3;
        float2 v = *(const float2*)&h_in[(size_t)src * 64 + 2 * lane];
        if (r == 0)      { c0++; a0.x += v.x; a0.y += v.y; }
        else if (r == 1) { c1++; a1.x += v.x; a1.y += v.y; }
        else             { c2++; a2.x += v.x; a2.y += v.y; }
    }
    float s0 = 1.f / (float)((c0 > 1) ? c0 : 1);
    float s1 = 1.f / (float)((c1 > 1) ? c1 : 1);
    float s2 = 1.f / (float)((c2 > 1) ? c2 : 1);

    float* row = g_cat + (size_t)node * 256;
    *(float2*)&row[0 + 2 * lane]   = make_float2(a0.x * s0, a0.y * s0);
    *(float2*)&row[64 + 2 * lane]  = make_float2(a1.x * s1, a1.y * s1);
    *(float2*)&row[128 + 2 * lane] = make_float2(a2.x * s2, a2.y * s2);
    *(float2*)&row[192 + 2 * lane] = hh;
}

// ---------------- GEMM: C[N,64] = relu(Acat[N,K] @ [w_rel;w_root] + b) ----------------
// 128 nodes per block tile (16 per warp); KC=32 chunks, cp.async double-buffered;
// f32x2 packed FMA; A reads are smem broadcasts.
template <int K>
__global__ void __launch_bounds__(256)
k_gemm(const float* __restrict__ A,
       const float* __restrict__ w_rel, const float* __restrict__ w_root,
       const float* __restrict__ bias,
       float* __restrict__ C, int n) {
    constexpr int F = K / 4;
    constexpr int KC = 32;
    constexpr int NC = K / KC;
    constexpr int AP = KC + 4;              // 36 floats per node-chunk row

    extern __shared__ float sm[];
    float* W_sm = sm;                       // [K][64]
    float* A_sm = sm + K * 64;              // [2][128][AP]

    {
        const float4* wr4 = (const float4*)w_rel;
        const float4* wo4 = (const float4*)w_root;
        constexpr int NREL4 = 3 * F * 64 / 4;
        constexpr int NW4 = K * 64 / 4;
        float4* W4 = (float4*)W_sm;
        for (int i = threadIdx.x; i < NW4; i += 256)
            W4[i] = (i < NREL4) ? __ldg(&wr4[i]) : __ldg(&wo4[i - NREL4]);
    }

    const int lane = threadIdx.x & 31;
    const int warp = threadIdx.x >> 5;
    const float2 bb = *(const float2*)&bias[2 * lane];

    const int nloc = threadIdx.x >> 1;      // 0..127 node slot
    const int seg  = threadIdx.x & 1;       // 16-float half of the 32-float chunk
    const unsigned int a_base = smem_u32(A_sm);

    for (int base = blockIdx.x * 128; base < n; base += gridDim.x * 128) {
        {
            int node = min(base + nloc, n - 1);
            const float* src = A + (size_t)node * K + seg * 16;
            unsigned int dst = a_base + (unsigned int)((nloc * AP + seg * 16) * 4);
#pragma unroll
            for (int v = 0; v < 4; v++) CP_ASYNC16(dst + v * 16, src + v * 4);
        }
        CP_COMMIT();

        float2 acc[16];
#pragma unroll
        for (int i = 0; i < 16; i++) acc[i] = make_float2(0.f, 0.f);

        for (int c = 0; c < NC; c++) {
            CP_WAIT0();
            __syncthreads();
            if (c + 1 < NC) {
                int node = min(base + nloc, n - 1);
                const float* src = A + (size_t)node * K + (c + 1) * KC + seg * 16;
                unsigned int dst = a_base +
                    (unsigned int)((((c + 1) & 1) * 128 * AP + nloc * AP + seg * 16) * 4);
#pragma unroll
                for (int v = 0; v < 4; v++) CP_ASYNC16(dst + v * 16, src + v * 4);
                CP_COMMIT();
            }
            const float* Ab = A_sm + (c & 1) * 128 * AP + (warp * 16) * AP;
            const float* Wb = W_sm + c * KC * 64;
#pragma unroll
            for (int k4 = 0; k4 < KC / 4; k4++) {
                float2 w0 = *(const float2*)&Wb[(4 * k4 + 0) * 64 + 2 * lane];
                float2 w1 = *(const float2*)&Wb[(4 * k4 + 1) * 64 + 2 * lane];
                float2 w2 = *(const float2*)&Wb[(4 * k4 + 2) * 64 + 2 * lane];
                float2 w3 = *(const float2*)&Wb[(4 * k4 + 3) * 64 + 2 * lane];
#pragma unroll
                for (int i = 0; i < 16; i++) {
                    float4 a = *(const float4*)&Ab[i * AP + 4 * k4];
                    acc[i] = ffma2(a.x, w0, acc[i]);
                    acc[i] = ffma2(a.y, w1, acc[i]);
                    acc[i] = ffma2(a.z, w2, acc[i]);
                    acc[i] = ffma2(a.w, w3, acc[i]);
                }
            }
            __syncthreads();
        }
#pragma unroll
        for (int i = 0; i < 16; i++) {
            int node = base + warp * 16 + i;
            if (node < n) {
                float2 r;
                r.x = fmaxf(acc[i].x + bb.x, 0.f);
                r.y = fmaxf(acc[i].y + bb.y, 0.f);
                *(float2*)&C[(size_t)node * 64 + 2 * lane] = r;
            }
        }
    }
}

// ---------------- classifier ----------------
__global__ void k_cls(const int* __restrict__ ptr,
                      const float* __restrict__ cls_w,
                      const float* __restrict__ cls_b,
                      float* __restrict__ out,
                      int nG) {
    int t = blockIdx.x * blockDim.x + threadIdx.x;
    if (t >= nG * 10) return;
    int g = t / 10;
    int c = t % 10;
    int idx = __ldg(&ptr[g + 1]) - 1;
    const float* hrow = &g_h3[(size_t)idx * 64];
    float s = __ldg(&cls_b[c]);
#pragma unroll
    for (int k = 0; k < 64; k++) s += hrow[k] * __ldg(&cls_w[k * 10 + c]);
    out[t] = s;
}

// ---------------- launch ----------------
extern "C" void kernel_launch(void* const* d_in, const int* in_sizes, int n_in,
                              void* d_out, int out_size) {
    const int* x          = (const int*)d_in[0];
    const int* edge_index = (const int*)d_in[1];
    const int* edge_type  = (const int*)d_in[2];
    const int* ptr        = (const int*)d_in[3];
    const float* shape_emb = (const float*)d_in[4];
    const float* color_emb = (const float*)d_in[5];
    const float* pre_w    = (const float*)d_in[6];
    const float* pre_b    = (const float*)d_in[7];
    const float* w1_rel   = (const float*)d_in[8];
    const float* w1_root  = (const float*)d_in[9];
    const float* b1       = (const float*)d_in[10];
    const float* w2_rel   = (const float*)d_in[11];
    const float* w2_root  = (const float*)d_in[12];
    const float* b2       = (const float*)d_in[13];
    const float* cls_w    = (const float*)d_in[14];
    const float* cls_b    = (const float*)d_in[15];
    float* out = (float*)d_out;

    const int nN = in_sizes[0] / 2;
    const int nE = in_sizes[2];
    const int nG = in_sizes[3] - 1;
    const int nb = (nN + SCAN_TILE - 1) / SCAN_TILE;

    float *h1, *h2, *h3, *cat;
    cudaGetSymbolAddress((void**)&h1, g_h1);
    cudaGetSymbolAddress((void**)&h2, g_h2);
    cudaGetSymbolAddress((void**)&h3, g_h3);
    cudaGetSymbolAddress((void**)&cat, g_cat);

    const int smem_g1 = (128 * 64 + 2 * 128 * 36) * (int)sizeof(float);   // 69632
    const int smem_g2 = (256 * 64 + 2 * 128 * 36) * (int)sizeof(float);   // 102400
    cudaFuncSetAttribute(k_gemm<128>, cudaFuncAttributeMaxDynamicSharedMemorySize, smem_g1);
    cudaFuncSetAttribute(k_gemm<256>, cudaFuncAttributeMaxDynamicSharedMemorySize, smem_g2);

    // CSR by destination
    k_zero_deg<<<(nN + 255) / 256, 256>>>(nN);
    k_count_deg<<<(nE + 255) / 256, 256>>>(edge_index, nE);
    k_scan_reduce<<<nb, SCAN_T>>>(nN);
    k_scan_mid<<<1, NB_MAX>>>(nb, nN);
    k_scan_final<<<nb, SCAN_T>>>(nN);
    k_fill_adj<<<(nE + 255) / 256, 256>>>(edge_index, edge_type, nE);

    // Feature pipeline
    k_pre<<<(nN * 32 + 255) / 256, 256>>>(x, shape_emb, color_emb, pre_w, pre_b, nN);

    k_agg32<<<(nN + 7) / 8, 256>>>(h1, nN);
    k_gemm<128><<<NSM * 3, 256, smem_g1>>>(cat, w1_rel, w1_root, b1, h2, nN);

    k_agg64<<<(nN + 7) / 8, 256>>>(h2, nN);
    k_gemm<256><<<NSM * 2, 256, smem_g2>>>(cat, w2_rel, w2_root, b2, h3, nN);

    k_cls<<<(nG * 10 + 255) / 256, 256>>>(ptr, cls_w, cls_b, out, nG);
}

// round 13
// speedup vs baseline: 2.2595x; 1.4677x over previous
#include <cuda_runtime.h>
#include <cuda_bf16.h>
#include <cstdint>
#include <cstdio>

#define MAXN 500000
#define MAXE 1000000
#define NB_MAX 512
#define SCAN_T 1024
#define SCAN_TILE 2048
#define NSM 152
#define MAXT64 ((MAXN + 63) / 64)
#define MAXNP (MAXT64 * 64)

// ---------------- scratch (device globals; no allocations) ----------------
__device__ int g_deg[MAXN];
__device__ int g_rowptr[MAXN + 1];
__device__ int g_cursor[MAXN];
__device__ int g_adj[MAXE];
__device__ int g_bsums[NB_MAX];
__device__ float g_h1[MAXN * 32];
__device__ float g_h2[MAXN * 64];
__device__ float g_h3[MAXN * 64];
// bf16 hi/lo A planes, row-major [node][K] (K=128 layer1, K=256 layer2)
__device__ unsigned short g_Ah[(size_t)MAXNP * 256];
__device__ unsigned short g_Al[(size_t)MAXNP * 256];

// ---------------- helpers ----------------
__device__ __forceinline__ uint32_t smem_u32(const void* p) {
    return (uint32_t)__cvta_generic_to_shared(p);
}
#define CP_ASYNC16(dst, src) \
    asm volatile("cp.async.cg.shared.global [%0], [%1], 16;" :: "r"(dst), "l"(src))
#define CP_COMMIT() asm volatile("cp.async.commit_group;")
#define CP_WAIT0()  asm volatile("cp.async.wait_group 0;" ::: "memory")

#define LDSM4(r0, r1, r2, r3, addr) \
    asm volatile("ldmatrix.sync.aligned.m8n8.x4.shared.b16 {%0,%1,%2,%3}, [%4];" \
        : "=r"(r0), "=r"(r1), "=r"(r2), "=r"(r3) : "r"(addr))
#define LDSM4T(r0, r1, r2, r3, addr) \
    asm volatile("ldmatrix.sync.aligned.m8n8.x4.trans.shared.b16 {%0,%1,%2,%3}, [%4];" \
        : "=r"(r0), "=r"(r1), "=r"(r2), "=r"(r3) : "r"(addr))
#define MMA16816(c0, c1, c2, c3, a0, a1, a2, a3, b0, b1) \
    asm volatile("mma.sync.aligned.m16n8k16.row.col.f32.bf16.bf16.f32 " \
        "{%0,%1,%2,%3}, {%4,%5,%6,%7}, {%8,%9}, {%0,%1,%2,%3};" \
        : "+f"(c0), "+f"(c1), "+f"(c2), "+f"(c3) \
        : "r"(a0), "r"(a1), "r"(a2), "r"(a3), "r"(b0), "r"(b1))

__device__ __forceinline__ void split_bf16(float x, unsigned short& h, unsigned short& l) {
    __nv_bfloat16 bh = __float2bfloat16(x);
    float r = x - __bfloat162float(bh);
    __nv_bfloat16 bl = __float2bfloat16(r);
    h = *reinterpret_cast<unsigned short*>(&bh);
    l = *reinterpret_cast<unsigned short*>(&bl);
}

// ---------------- CSR build ----------------
__global__ void k_zero_deg(int n) {
    int t = blockIdx.x * blockDim.x + threadIdx.x;
    if (t < n) g_deg[t] = 0;
}
__global__ void k_count_deg(const int* __restrict__ ei, int nE) {
    int e = blockIdx.x * blockDim.x + threadIdx.x;
    if (e >= nE) return;
    atomicAdd(&g_deg[ei[nE + e]], 1);
}
__global__ void k_scan_reduce(int n) {
    __shared__ int sd[SCAN_T];
    int base = blockIdx.x * SCAN_TILE + threadIdx.x * 2;
    int s = 0;
    if (base < n) s += g_deg[base];
    if (base + 1 < n) s += g_deg[base + 1];
    sd[threadIdx.x] = s;
    __syncthreads();
    for (int d = SCAN_T / 2; d > 0; d >>= 1) {
        if (threadIdx.x < d) sd[threadIdx.x] += sd[threadIdx.x + d];
        __syncthreads();
    }
    if (threadIdx.x == 0) g_bsums[blockIdx.x] = sd[0];
}
__global__ void k_scan_mid(int nb, int nN) {
    __shared__ int sd[NB_MAX];
    int tid = threadIdx.x;
    int v0 = (tid < nb) ? g_bsums[tid] : 0;
    sd[tid] = v0;
    __syncthreads();
    for (int d = 1; d < NB_MAX; d <<= 1) {
        int v = (tid >= d) ? sd[tid - d] : 0;
        __syncthreads();
        sd[tid] += v;
        __syncthreads();
    }
    if (tid < nb) g_bsums[tid] = sd[tid] - v0;
    if (tid == NB_MAX - 1) g_rowptr[nN] = sd[NB_MAX - 1];
}
__global__ void k_scan_final(int n) {
    __shared__ int sd[SCAN_T];
    int tid = threadIdx.x;
    int base = blockIdx.x * SCAN_TILE + tid * 2;
    int t0 = (base < n) ? g_deg[base] : 0;
    int t1 = (base + 1 < n) ? g_deg[base + 1] : 0;
    int ts = t0 + t1;
    sd[tid] = ts;
    __syncthreads();
    for (int d = 1; d < SCAN_T; d <<= 1) {
        int v = (tid >= d) ? sd[tid - d] : 0;
        __syncthreads();
        sd[tid] += v;
        __syncthreads();
    }
    int excl = sd[tid] - ts + g_bsums[blockIdx.x];
    if (base < n)     { g_rowptr[base]     = excl;      g_cursor[base]     = excl; }
    if (base + 1 < n) { g_rowptr[base + 1] = excl + t0; g_cursor[base + 1] = excl + t0; }
}
__global__ void k_fill_adj(const int* __restrict__ ei, const int* __restrict__ et, int nE) {
    int e = blockIdx.x * blockDim.x + threadIdx.x;
    if (e >= nE) return;
    int src = ei[e];
    int dst = ei[nE + e];
    int r = et[e];
    int pos = atomicAdd(&g_cursor[dst], 1);
    g_adj[pos] = (src << 2) | r;
}

// ---------------- pre-MLP ----------------
__global__ void k_pre(const int* __restrict__ x,
                      const float* __restrict__ shape_emb,
                      const float* __restrict__ color_emb,
                      const float* __restrict__ pre_w,
                      const float* __restrict__ pre_b,
                      int n) {
    int t = blockIdx.x * blockDim.x + threadIdx.x;
    if (t >= n * 32) return;
    int node = t >> 5;
    int f = t & 31;
    int si = __ldg(&x[2 * node]);
    int ci = __ldg(&x[2 * node + 1]);
    float s = __ldg(&pre_b[f]);
#pragma unroll
    for (int k = 0; k < 8; k++)
        s += __ldg(&shape_emb[si * 8 + k]) * __ldg(&pre_w[k * 32 + f]);
#pragma unroll
    for (int k = 0; k < 8; k++)
        s += __ldg(&color_emb[ci * 8 + k]) * __ldg(&pre_w[(8 + k) * 32 + f]);
    g_h1[node * 32 + f] = fmaxf(s, 0.f);
}

// ---------------- aggregation F=32 -> bf16 hi/lo planes [node][128] ----------------
__global__ void __launch_bounds__(256)
k_agg32(const float* __restrict__ h_in, int n, int npad) {
    int node = blockIdx.x * 8 + (threadIdx.x >> 5);
    if (node >= npad) return;
    const int lane = threadIdx.x & 31;
    float vals[4] = {0.f, 0.f, 0.f, 0.f};

    if (node < n) {
        float hh = __ldg(&h_in[(size_t)node * 32 + lane]);
        float a0 = 0.f, a1 = 0.f, a2 = 0.f;
        int c0 = 0, c1 = 0, c2 = 0;
        int rs = __ldg(&g_rowptr[node]);
        int re = __ldg(&g_rowptr[node + 1]);
#pragma unroll 4
        for (int e = rs; e < re; ++e) {
            int p = __ldg(&g_adj[e]);
            int src = p >> 2;
            int r = p & 3;
            float v = __ldg(&h_in[(size_t)src * 32 + lane]);
            if (r == 0)      { c0++; a0 += v; }
            else if (r == 1) { c1++; a1 += v; }
            else             { c2++; a2 += v; }
        }
        vals[0] = a0 / (float)((c0 > 1) ? c0 : 1);
        vals[1] = a1 / (float)((c1 > 1) ? c1 : 1);
        vals[2] = a2 / (float)((c2 > 1) ? c2 : 1);
        vals[3] = hh;
    }
    size_t base = (size_t)node * 128;
#pragma unroll
    for (int s = 0; s < 4; s++) {
        unsigned short h, l;
        split_bf16(vals[s], h, l);
        g_Ah[base + s * 32 + lane] = h;
        g_Al[base + s * 32 + lane] = l;
    }
}

// ---------------- aggregation F=64 -> bf16 hi/lo planes [node][256] ----------------
__global__ void __launch_bounds__(256)
k_agg64(const float* __restrict__ h_in, int n, int npad) {
    int node = blockIdx.x * 8 + (threadIdx.x >> 5);
    if (node >= npad) return;
    const int lane = threadIdx.x & 31;
    float2 vals[4];
#pragma unroll
    for (int s = 0; s < 4; s++) vals[s] = make_float2(0.f, 0.f);

    if (node < n) {
        float2 hh = *(const float2*)&h_in[(size_t)node * 64 + 2 * lane];
        float2 a0 = make_float2(0.f, 0.f), a1 = a0, a2 = a0;
        int c0 = 0, c1 = 0, c2 = 0;
        int rs = __ldg(&g_rowptr[node]);
        int re = __ldg(&g_rowptr[node + 1]);
#pragma unroll 4
        for (int e = rs; e < re; ++e) {
            int p = __ldg(&g_adj[e]);
            int src = p >> 2;
            int r = p & 3;
            float2 v = *(const float2*)&h_in[(size_t)src * 64 + 2 * lane];
            if (r == 0)      { c0++; a0.x += v.x; a0.y += v.y; }
            else if (r == 1) { c1++; a1.x += v.x; a1.y += v.y; }
            else             { c2++; a2.x += v.x; a2.y += v.y; }
        }
        float s0 = 1.f / (float)((c0 > 1) ? c0 : 1);
        float s1 = 1.f / (float)((c1 > 1) ? c1 : 1);
        float s2 = 1.f / (float)((c2 > 1) ? c2 : 1);
        vals[0] = make_float2(a0.x * s0, a0.y * s0);
        vals[1] = make_float2(a1.x * s1, a1.y * s1);
        vals[2] = make_float2(a2.x * s2, a2.y * s2);
        vals[3] = hh;
    }
    size_t base = (size_t)node * 256;
#pragma unroll
    for (int s = 0; s < 4; s++) {
        unsigned short h0, l0, h1, l1;
        split_bf16(vals[s].x, h0, l0);
        split_bf16(vals[s].y, h1, l1);
        *(unsigned int*)&g_Ah[base + s * 64 + 2 * lane] = (unsigned int)h0 | ((unsigned int)h1 << 16);
        *(unsigned int*)&g_Al[base + s * 64 + 2 * lane] = (unsigned int)l0 | ((unsigned int)l1 << 16);
    }
}

// ---------------- HMMA GEMM: C[N,64] = relu(A[N,K] @ [w_rel;w_root] + b) ----------------
// Persistent; W hi/lo [K][72] in smem once; A tiles (64 rows) double-buffered via
// cp.async; per warp: rows 16*(wid&3), cols 32*(wid>>2); bf16 mma with 3-way split.
template <int K>
__global__ void __launch_bounds__(256)
k_gemm_hmma(const float* __restrict__ w_rel, const float* __restrict__ w_root,
            const float* __restrict__ bias,
            float* __restrict__ C, int n) {
    constexpr int F = K / 4;
    constexpr int NK = K / 16;
    constexpr int ROWW = K + 8;           // bf16 units per A smem row
    constexpr int WROW = 72;              // bf16 units per W smem row
    constexpr int ABUF = 64 * ROWW;       // u16 per A plane buffer
    constexpr int CH = (K * 2) / 16;      // 16B chunks per A row

    extern __shared__ unsigned short sh[];
    unsigned short* Wh = sh;                          // [K][72]
    unsigned short* Wl = Wh + K * WROW;
    unsigned short* Ab = Wl + K * WROW;               // [2 bufs][2 planes][64][ROWW]

    const int tid = threadIdx.x;
    const int lane = tid & 31;
    const int wid = tid >> 5;

    // build W hi/lo: [k][n] row-major
    for (int i = tid; i < 64 * K; i += 256) {
        int k = i >> 6, nn = i & 63;
        float w = (k < 3 * F) ? __ldg(&w_rel[i]) : __ldg(&w_root[i - 3 * F * 64]);
        unsigned short h, l;
        split_bf16(w, h, l);
        Wh[k * WROW + nn] = h;
        Wl[k * WROW + nn] = l;
    }
    __syncthreads();

    const int ntiles = (n + 63) / 64;
    const char* gAh = (const char*)g_Ah;
    const char* gAl = (const char*)g_Al;
    const uint32_t aSm = smem_u32(Ab);

    // ldmatrix lane addressing
    const int wr = wid & 3, wc = wid >> 2;
    const uint32_t aOff = (uint32_t)(((wr * 16 + (lane & 15)) * ROWW + 8 * (lane >> 4)) * 2);
    const uint32_t bOff = (uint32_t)(((((lane & 7) + 8 * ((lane >> 3) & 1)) * WROW) +
                                     wc * 32 + 8 * (lane >> 4)) * 2);
    const uint32_t bhSm = smem_u32(Wh) + bOff;
    const uint32_t blSm = smem_u32(Wl) + bOff;

    // prefetch first tile into buf 0
    if (blockIdx.x < ntiles) {
        size_t gb = (size_t)blockIdx.x * 64 * K * 2;
        for (int c = tid; c < 64 * CH; c += 256) {
            int row = c / CH, ci = c % CH;
            uint32_t d = aSm + (uint32_t)((row * ROWW) * 2 + ci * 16);
            const char* s = gAh + gb + (size_t)row * K * 2 + ci * 16;
            CP_ASYNC16(d, s);
            CP_ASYNC16(d + ABUF * 2, gAl + gb + (size_t)row * K * 2 + ci * 16);
        }
    }
    CP_COMMIT();

    int it = 0;
    for (int tile = blockIdx.x; tile < ntiles; tile += gridDim.x, ++it) {
        const int cur = it & 1;
        CP_WAIT0();
        __syncthreads();

        // prefetch next tile into other buffer
        int nt = tile + gridDim.x;
        if (nt < ntiles) {
            size_t gb = (size_t)nt * 64 * K * 2;
            uint32_t bufb = aSm + (uint32_t)((cur ^ 1) * 2 * ABUF * 2);
            for (int c = tid; c < 64 * CH; c += 256) {
                int row = c / CH, ci = c % CH;
                uint32_t d = bufb + (uint32_t)((row * ROWW) * 2 + ci * 16);
                CP_ASYNC16(d, gAh + gb + (size_t)row * K * 2 + ci * 16);
                CP_ASYNC16(d + ABUF * 2, gAl + gb + (size_t)row * K * 2 + ci * 16);
            }
        }
        CP_COMMIT();

        float c0[4], c1[4], c2[4], c3[4];
#pragma unroll
        for (int i = 0; i < 4; i++) { c0[i] = 0.f; c1[i] = 0.f; c2[i] = 0.f; c3[i] = 0.f; }

        const uint32_t curBase = aSm + (uint32_t)(cur * 2 * ABUF * 2);
#pragma unroll
        for (int s = 0; s < 3; s++) {
            const uint32_t aBase = curBase + (s == 2 ? (uint32_t)(ABUF * 2) : 0u) + aOff;
            const uint32_t bBase = (s == 1) ? blSm : bhSm;
#pragma unroll
            for (int ks = 0; ks < NK; ks++) {
                uint32_t a0, a1, a2, a3;
                LDSM4(a0, a1, a2, a3, aBase + (uint32_t)(ks * 32));
                uint32_t b0, b1, b2, b3, b4, b5, b6, b7;
                LDSM4T(b0, b1, b2, b3, bBase + (uint32_t)(ks * 16 * WROW * 2));
                LDSM4T(b4, b5, b6, b7, bBase + (uint32_t)(ks * 16 * WROW * 2 + 32));
                MMA16816(c0[0], c0[1], c0[2], c0[3], a0, a1, a2, a3, b0, b1);
                MMA16816(c1[0], c1[1], c1[2], c1[3], a0, a1, a2, a3, b2, b3);
                MMA16816(c2[0], c2[1], c2[2], c2[3], a0, a1, a2, a3, b4, b5);
                MMA16816(c3[0], c3[1], c3[2], c3[3], a0, a1, a2, a3, b6, b7);
            }
        }

        // epilogue
        const int r0 = wr * 16 + (lane >> 2);
        const int cbase = wc * 32 + 2 * (lane & 3);
        const int m0 = tile * 64 + r0;
        float* cc[4] = {c0, c1, c2, c3};
#pragma unroll
        for (int nb = 0; nb < 4; nb++) {
            int col = cbase + nb * 8;
            float2 bb = *(const float2*)&bias[col];
            if (m0 < n) {
                float2 o;
                o.x = fmaxf(cc[nb][0] + bb.x, 0.f);
                o.y = fmaxf(cc[nb][1] + bb.y, 0.f);
                *(float2*)&C[(size_t)m0 * 64 + col] = o;
            }
            if (m0 + 8 < n) {
                float2 o;
                o.x = fmaxf(cc[nb][2] + bb.x, 0.f);
                o.y = fmaxf(cc[nb][3] + bb.y, 0.f);
                *(float2*)&C[(size_t)(m0 + 8) * 64 + col] = o;
            }
        }
    }
}

// ---------------- classifier ----------------
__global__ void k_cls(const int* __restrict__ ptr,
                      const float* __restrict__ cls_w,
                      const float* __restrict__ cls_b,
                      float* __restrict__ out,
                      int nG) {
    int t = blockIdx.x * blockDim.x + threadIdx.x;
    if (t >= nG * 10) return;
    int g = t / 10;
    int c = t % 10;
    int idx = __ldg(&ptr[g + 1]) - 1;
    const float* hrow = &g_h3[(size_t)idx * 64];
    float s = __ldg(&cls_b[c]);
#pragma unroll
    for (int k = 0; k < 64; k++) s += hrow[k] * __ldg(&cls_w[k * 10 + c]);
    out[t] = s;
}

// ---------------- launch ----------------
extern "C" void kernel_launch(void* const* d_in, const int* in_sizes, int n_in,
                              void* d_out, int out_size) {
    const int* x          = (const int*)d_in[0];
    const int* edge_index = (const int*)d_in[1];
    const int* edge_type  = (const int*)d_in[2];
    const int* ptr        = (const int*)d_in[3];
    const float* shape_emb = (const float*)d_in[4];
    const float* color_emb = (const float*)d_in[5];
    const float* pre_w    = (const float*)d_in[6];
    const float* pre_b    = (const float*)d_in[7];
    const float* w1_rel   = (const float*)d_in[8];
    const float* w1_root  = (const float*)d_in[9];
    const float* b1       = (const float*)d_in[10];
    const float* w2_rel   = (const float*)d_in[11];
    const float* w2_root  = (const float*)d_in[12];
    const float* b2       = (const float*)d_in[13];
    const float* cls_w    = (const float*)d_in[14];
    const float* cls_b    = (const float*)d_in[15];
    float* out = (float*)d_out;

    const int nN = in_sizes[0] / 2;
    const int nE = in_sizes[2];
    const int nG = in_sizes[3] - 1;
    const int nb = (nN + SCAN_TILE - 1) / SCAN_TILE;
    const int ntiles = (nN + 63) / 64;
    const int npad = ntiles * 64;

    float *h1, *h2, *h3;
    cudaGetSymbolAddress((void**)&h1, g_h1);
    cudaGetSymbolAddress((void**)&h2, g_h2);
    cudaGetSymbolAddress((void**)&h3, g_h3);

    // smem: W 2*K*72*2 bytes + A 2 bufs * 2 planes * 64*(K+8)*2 bytes
    const int smem1 = 2 * 128 * 72 * 2 + 4 * 64 * 136 * 2;   // 36864 + 69632 = 106496
    const int smem2 = 2 * 256 * 72 * 2 + 4 * 64 * 264 * 2;   // 73728 + 135168 = 208896
    cudaFuncSetAttribute((const void*)k_gemm_hmma<128>,
                         cudaFuncAttributeMaxDynamicSharedMemorySize, smem1);
    cudaFuncSetAttribute((const void*)k_gemm_hmma<256>,
                         cudaFuncAttributeMaxDynamicSharedMemorySize, smem2);

    // CSR by destination
    k_zero_deg<<<(nN + 255) / 256, 256>>>(nN);
    k_count_deg<<<(nE + 255) / 256, 256>>>(edge_index, nE);
    k_scan_reduce<<<nb, SCAN_T>>>(nN);
    k_scan_mid<<<1, NB_MAX>>>(nb, nN);
    k_scan_final<<<nb, SCAN_T>>>(nN);
    k_fill_adj<<<(nE + 255) / 256, 256>>>(edge_index, edge_type, nE);

    // Feature pipeline
    k_pre<<<(nN * 32 + 255) / 256, 256>>>(x, shape_emb, color_emb, pre_w, pre_b, nN);

    k_agg32<<<(npad + 7) / 8, 256>>>(h1, nN, npad);
    k_gemm_hmma<128><<<NSM * 2, 256, smem1>>>(w1_rel, w1_root, b1, h2, nN);

    k_agg64<<<(npad + 7) / 8, 256>>>(h2, nN, npad);
    k_gemm_hmma<256><<<NSM, 256, smem2>>>(w2_rel, w2_root, b2, h3, nN);

    k_cls<<<(nG * 10 + 255) / 256, 256>>>(ptr, cls_w, cls_b, out, nG);
}

// round 14
// speedup vs baseline: 2.8595x; 1.2656x over previous
#include <cuda_runtime.h>
#include <cuda_fp16.h>
#include <cstdint>
#include <cstdio>

#define MAXN 500000
#define MAXE 1000000
#define NB_MAX 512
#define SCAN_T 1024
#define SCAN_TILE 2048
#define NSM 152
#define MAXT64 ((MAXN + 63) / 64)
#define MAXNP (MAXT64 * 64)

// ---------------- scratch (device globals; no allocations) ----------------
__device__ int g_deg[MAXN];
__device__ int g_rowptr[MAXN + 1];
__device__ int g_cursor[MAXN];
__device__ int g_adj[MAXE];
__device__ int g_bsums[NB_MAX];
__device__ float g_h1[MAXN * 32];
__device__ float g_h2[MAXN * 64];
__device__ float g_h3[MAXN * 64];
// fp16 A plane, row-major [node][K] (K=128 layer1, K=256 layer2)
__device__ unsigned short g_A[(size_t)MAXNP * 256];

// ---------------- helpers ----------------
__device__ __forceinline__ uint32_t smem_u32(const void* p) {
    return (uint32_t)__cvta_generic_to_shared(p);
}
#define CP_ASYNC16(dst, src) \
    asm volatile("cp.async.cg.shared.global [%0], [%1], 16;" :: "r"(dst), "l"(src))
#define CP_COMMIT() asm volatile("cp.async.commit_group;")
#define CP_WAIT0()  asm volatile("cp.async.wait_group 0;" ::: "memory")

#define LDSM4(r0, r1, r2, r3, addr) \
    asm volatile("ldmatrix.sync.aligned.m8n8.x4.shared.b16 {%0,%1,%2,%3}, [%4];" \
        : "=r"(r0), "=r"(r1), "=r"(r2), "=r"(r3) : "r"(addr))
#define LDSM4T(r0, r1, r2, r3, addr) \
    asm volatile("ldmatrix.sync.aligned.m8n8.x4.trans.shared.b16 {%0,%1,%2,%3}, [%4];" \
        : "=r"(r0), "=r"(r1), "=r"(r2), "=r"(r3) : "r"(addr))
#define MMA16816F16(c0, c1, c2, c3, a0, a1, a2, a3, b0, b1) \
    asm volatile("mma.sync.aligned.m16n8k16.row.col.f32.f16.f16.f32 " \
        "{%0,%1,%2,%3}, {%4,%5,%6,%7}, {%8,%9}, {%0,%1,%2,%3};" \
        : "+f"(c0), "+f"(c1), "+f"(c2), "+f"(c3) \
        : "r"(a0), "r"(a1), "r"(a2), "r"(a3), "r"(b0), "r"(b1))

__device__ __forceinline__ unsigned short f2h(float x) {
    __half h = __float2half_rn(x);
    return *reinterpret_cast<unsigned short*>(&h);
}

// ---------------- CSR build ----------------
__global__ void k_zero_deg(int n) {
    int t = blockIdx.x * blockDim.x + threadIdx.x;
    if (t < n) g_deg[t] = 0;
}
__global__ void k_count_deg(const int* __restrict__ ei, int nE) {
    int e = blockIdx.x * blockDim.x + threadIdx.x;
    if (e >= nE) return;
    atomicAdd(&g_deg[ei[nE + e]], 1);
}
__global__ void k_scan_reduce(int n) {
    __shared__ int sd[SCAN_T];
    int base = blockIdx.x * SCAN_TILE + threadIdx.x * 2;
    int s = 0;
    if (base < n) s += g_deg[base];
    if (base + 1 < n) s += g_deg[base + 1];
    sd[threadIdx.x] = s;
    __syncthreads();
    for (int d = SCAN_T / 2; d > 0; d >>= 1) {
        if (threadIdx.x < d) sd[threadIdx.x] += sd[threadIdx.x + d];
        __syncthreads();
    }
    if (threadIdx.x == 0) g_bsums[blockIdx.x] = sd[0];
}
__global__ void k_scan_mid(int nb, int nN) {
    __shared__ int sd[NB_MAX];
    int tid = threadIdx.x;
    int v0 = (tid < nb) ? g_bsums[tid] : 0;
    sd[tid] = v0;
    __syncthreads();
    for (int d = 1; d < NB_MAX; d <<= 1) {
        int v = (tid >= d) ? sd[tid - d] : 0;
        __syncthreads();
        sd[tid] += v;
        __syncthreads();
    }
    if (tid < nb) g_bsums[tid] = sd[tid] - v0;
    if (tid == NB_MAX - 1) g_rowptr[nN] = sd[NB_MAX - 1];
}
__global__ void k_scan_final(int n) {
    __shared__ int sd[SCAN_T];
    int tid = threadIdx.x;
    int base = blockIdx.x * SCAN_TILE + tid * 2;
    int t0 = (base < n) ? g_deg[base] : 0;
    int t1 = (base + 1 < n) ? g_deg[base + 1] : 0;
    int ts = t0 + t1;
    sd[tid] = ts;
    __syncthreads();
    for (int d = 1; d < SCAN_T; d <<= 1) {
        int v = (tid >= d) ? sd[tid - d] : 0;
        __syncthreads();
        sd[tid] += v;
        __syncthreads();
    }
    int excl = sd[tid] - ts + g_bsums[blockIdx.x];
    if (base < n)     { g_rowptr[base]     = excl;      g_cursor[base]     = excl; }
    if (base + 1 < n) { g_rowptr[base + 1] = excl + t0; g_cursor[base + 1] = excl + t0; }
}
__global__ void k_fill_adj(const int* __restrict__ ei, const int* __restrict__ et, int nE) {
    int e = blockIdx.x * blockDim.x + threadIdx.x;
    if (e >= nE) return;
    int src = ei[e];
    int dst = ei[nE + e];
    int r = et[e];
    int pos = atomicAdd(&g_cursor[dst], 1);
    g_adj[pos] = (src << 2) | r;
}

// ---------------- pre-MLP ----------------
__global__ void k_pre(const int* __restrict__ x,
                      const float* __restrict__ shape_emb,
                      const float* __restrict__ color_emb,
                      const float* __restrict__ pre_w,
                      const float* __restrict__ pre_b,
                      int n) {
    int t = blockIdx.x * blockDim.x + threadIdx.x;
    if (t >= n * 32) return;
    int node = t >> 5;
    int f = t & 31;
    int si = __ldg(&x[2 * node]);
    int ci = __ldg(&x[2 * node + 1]);
    float s = __ldg(&pre_b[f]);
#pragma unroll
    for (int k = 0; k < 8; k++)
        s += __ldg(&shape_emb[si * 8 + k]) * __ldg(&pre_w[k * 32 + f]);
#pragma unroll
    for (int k = 0; k < 8; k++)
        s += __ldg(&color_emb[ci * 8 + k]) * __ldg(&pre_w[(8 + k) * 32 + f]);
    g_h1[node * 32 + f] = fmaxf(s, 0.f);
}

// ---------------- aggregation F=32 -> fp16 A plane [node][128] ----------------
__global__ void __launch_bounds__(256)
k_agg32(const float* __restrict__ h_in, int n, int npad) {
    int node = blockIdx.x * 8 + (threadIdx.x >> 5);
    if (node >= npad) return;
    const int lane = threadIdx.x & 31;
    float vals[4] = {0.f, 0.f, 0.f, 0.f};

    if (node < n) {
        float hh = __ldg(&h_in[(size_t)node * 32 + lane]);
        float a0 = 0.f, a1 = 0.f, a2 = 0.f;
        int c0 = 0, c1 = 0, c2 = 0;
        int rs = __ldg(&g_rowptr[node]);
        int re = __ldg(&g_rowptr[node + 1]);
#pragma unroll 4
        for (int e = rs; e < re; ++e) {
            int p = __ldg(&g_adj[e]);
            int src = p >> 2;
            int r = p & 3;
            float v = __ldg(&h_in[(size_t)src * 32 + lane]);
            if (r == 0)      { c0++; a0 += v; }
            else if (r == 1) { c1++; a1 += v; }
            else             { c2++; a2 += v; }
        }
        vals[0] = a0 / (float)((c0 > 1) ? c0 : 1);
        vals[1] = a1 / (float)((c1 > 1) ? c1 : 1);
        vals[2] = a2 / (float)((c2 > 1) ? c2 : 1);
        vals[3] = hh;
    }
    size_t base = (size_t)node * 128;
#pragma unroll
    for (int s = 0; s < 4; s++)
        g_A[base + s * 32 + lane] = f2h(vals[s]);
}

// ---------------- aggregation F=64 -> fp16 A plane [node][256] ----------------
__global__ void __launch_bounds__(256)
k_agg64(const float* __restrict__ h_in, int n, int npad) {
    int node = blockIdx.x * 8 + (threadIdx.x >> 5);
    if (node >= npad) return;
    const int lane = threadIdx.x & 31;
    float2 vals[4];
#pragma unroll
    for (int s = 0; s < 4; s++) vals[s] = make_float2(0.f, 0.f);

    if (node < n) {
        float2 hh = *(const float2*)&h_in[(size_t)node * 64 + 2 * lane];
        float2 a0 = make_float2(0.f, 0.f), a1 = a0, a2 = a0;
        int c0 = 0, c1 = 0, c2 = 0;
        int rs = __ldg(&g_rowptr[node]);
        int re = __ldg(&g_rowptr[node + 1]);
#pragma unroll 4
        for (int e = rs; e < re; ++e) {
            int p = __ldg(&g_adj[e]);
            int src = p >> 2;
            int r = p & 3;
            float2 v = *(const float2*)&h_in[(size_t)src * 64 + 2 * lane];
            if (r == 0)      { c0++; a0.x += v.x; a0.y += v.y; }
            else if (r == 1) { c1++; a1.x += v.x; a1.y += v.y; }
            else             { c2++; a2.x += v.x; a2.y += v.y; }
        }
        float s0 = 1.f / (float)((c0 > 1) ? c0 : 1);
        float s1 = 1.f / (float)((c1 > 1) ? c1 : 1);
        float s2 = 1.f / (float)((c2 > 1) ? c2 : 1);
        vals[0] = make_float2(a0.x * s0, a0.y * s0);
        vals[1] = make_float2(a1.x * s1, a1.y * s1);
        vals[2] = make_float2(a2.x * s2, a2.y * s2);
        vals[3] = hh;
    }
    size_t base = (size_t)node * 256;
#pragma unroll
    for (int s = 0; s < 4; s++) {
        unsigned int packed = (unsigned int)f2h(vals[s].x) |
                              ((unsigned int)f2h(vals[s].y) << 16);
        *(unsigned int*)&g_A[base + s * 64 + 2 * lane] = packed;
    }
}

// ---------------- HMMA GEMM: C[N,64] = relu(A[N,K] @ [w_rel;w_root] + b) ----------------
// Persistent; fp16 W [K][72] in smem once; fp16 A tiles (64 rows) double-buffered
// via cp.async; per warp: rows 16*(wid&3), cols 32*(wid>>2); single-product fp16 mma.
template <int K>
__global__ void __launch_bounds__(256)
k_gemm_hmma(const float* __restrict__ w_rel, const float* __restrict__ w_root,
            const float* __restrict__ bias,
            float* __restrict__ C, int n) {
    constexpr int F = K / 4;
    constexpr int NK = K / 16;
    constexpr int ROWW = K + 8;           // fp16 units per A smem row
    constexpr int WROW = 72;              // fp16 units per W smem row
    constexpr int ABUF = 64 * ROWW;       // u16 per A buffer
    constexpr int CH = (K * 2) / 16;      // 16B chunks per A row

    extern __shared__ unsigned short sh[];
    unsigned short* Wf = sh;                          // [K][72]
    unsigned short* Ab = Wf + K * WROW;               // [2 bufs][64][ROWW]

    const int tid = threadIdx.x;
    const int lane = tid & 31;
    const int wid = tid >> 5;

    // build fp16 W: [k][n] row-major
    for (int i = tid; i < 64 * K; i += 256) {
        int k = i >> 6, nn = i & 63;
        float w = (k < 3 * F) ? __ldg(&w_rel[i]) : __ldg(&w_root[i - 3 * F * 64]);
        Wf[k * WROW + nn] = f2h(w);
    }
    __syncthreads();

    const int ntiles = (n + 63) / 64;
    const char* gA = (const char*)g_A;
    const uint32_t aSm = smem_u32(Ab);

    // ldmatrix lane addressing
    const int wr = wid & 3, wc = wid >> 2;
    const uint32_t aOff = (uint32_t)(((wr * 16 + (lane & 15)) * ROWW + 8 * (lane >> 4)) * 2);
    const uint32_t bOff = (uint32_t)(((((lane & 7) + 8 * ((lane >> 3) & 1)) * WROW) +
                                     wc * 32 + 8 * (lane >> 4)) * 2);
    const uint32_t bSm = smem_u32(Wf) + bOff;

    // prefetch first tile into buf 0
    if (blockIdx.x < ntiles) {
        size_t gb = (size_t)blockIdx.x * 64 * K * 2;
        for (int c = tid; c < 64 * CH; c += 256) {
            int row = c / CH, ci = c % CH;
            CP_ASYNC16(aSm + (uint32_t)((row * ROWW) * 2 + ci * 16),
                       gA + gb + (size_t)row * K * 2 + ci * 16);
        }
    }
    CP_COMMIT();

    int it = 0;
    for (int tile = blockIdx.x; tile < ntiles; tile += gridDim.x, ++it) {
        const int cur = it & 1;
        CP_WAIT0();
        __syncthreads();

        // prefetch next tile into other buffer
        int nt = tile + gridDim.x;
        if (nt < ntiles) {
            size_t gb = (size_t)nt * 64 * K * 2;
            uint32_t bufb = aSm + (uint32_t)((cur ^ 1) * ABUF * 2);
            for (int c = tid; c < 64 * CH; c += 256) {
                int row = c / CH, ci = c % CH;
                CP_ASYNC16(bufb + (uint32_t)((row * ROWW) * 2 + ci * 16),
                           gA + gb + (size_t)row * K * 2 + ci * 16);
            }
        }
        CP_COMMIT();

        float c0[4], c1[4], c2[4], c3[4];
#pragma unroll
        for (int i = 0; i < 4; i++) { c0[i] = 0.f; c1[i] = 0.f; c2[i] = 0.f; c3[i] = 0.f; }

        const uint32_t aBase = aSm + (uint32_t)(cur * ABUF * 2) + aOff;
#pragma unroll
        for (int ks = 0; ks < NK; ks++) {
            uint32_t a0, a1, a2, a3;
            LDSM4(a0, a1, a2, a3, aBase + (uint32_t)(ks * 32));
            uint32_t b0, b1, b2, b3, b4, b5, b6, b7;
            LDSM4T(b0, b1, b2, b3, bSm + (uint32_t)(ks * 16 * WROW * 2));
            LDSM4T(b4, b5, b6, b7, bSm + (uint32_t)(ks * 16 * WROW * 2 + 32));
            MMA16816F16(c0[0], c0[1], c0[2], c0[3], a0, a1, a2, a3, b0, b1);
            MMA16816F16(c1[0], c1[1], c1[2], c1[3], a0, a1, a2, a3, b2, b3);
            MMA16816F16(c2[0], c2[1], c2[2], c2[3], a0, a1, a2, a3, b4, b5);
            MMA16816F16(c3[0], c3[1], c3[2], c3[3], a0, a1, a2, a3, b6, b7);
        }

        // epilogue
        const int r0 = wr * 16 + (lane >> 2);
        const int cbase = wc * 32 + 2 * (lane & 3);
        const int m0 = tile * 64 + r0;
        float* cc[4] = {c0, c1, c2, c3};
#pragma unroll
        for (int nb = 0; nb < 4; nb++) {
            int col = cbase + nb * 8;
            float2 bb = *(const float2*)&bias[col];
            if (m0 < n) {
                float2 o;
                o.x = fmaxf(cc[nb][0] + bb.x, 0.f);
                o.y = fmaxf(cc[nb][1] + bb.y, 0.f);
                *(float2*)&C[(size_t)m0 * 64 + col] = o;
            }
            if (m0 + 8 < n) {
                float2 o;
                o.x = fmaxf(cc[nb][2] + bb.x, 0.f);
                o.y = fmaxf(cc[nb][3] + bb.y, 0.f);
                *(float2*)&C[(size_t)(m0 + 8) * 64 + col] = o;
            }
        }
    }
}

// ---------------- classifier ----------------
__global__ void k_cls(const int* __restrict__ ptr,
                      const float* __restrict__ cls_w,
                      const float* __restrict__ cls_b,
                      float* __restrict__ out,
                      int nG) {
    int t = blockIdx.x * blockDim.x + threadIdx.x;
    if (t >= nG * 10) return;
    int g = t / 10;
    int c = t % 10;
    int idx = __ldg(&ptr[g + 1]) - 1;
    const float* hrow = &g_h3[(size_t)idx * 64];
    float s = __ldg(&cls_b[c]);
#pragma unroll
    for (int k = 0; k < 64; k++) s += hrow[k] * __ldg(&cls_w[k * 10 + c]);
    out[t] = s;
}

// ---------------- launch ----------------
extern "C" void kernel_launch(void* const* d_in, const int* in_sizes, int n_in,
                              void* d_out, int out_size) {
    const int* x          = (const int*)d_in[0];
    const int* edge_index = (const int*)d_in[1];
    const int* edge_type  = (const int*)d_in[2];
    const int* ptr        = (const int*)d_in[3];
    const float* shape_emb = (const float*)d_in[4];
    const float* color_emb = (const float*)d_in[5];
    const float* pre_w    = (const float*)d_in[6];
    const float* pre_b    = (const float*)d_in[7];
    const float* w1_rel   = (const float*)d_in[8];
    const float* w1_root  = (const float*)d_in[9];
    const float* b1       = (const float*)d_in[10];
    const float* w2_rel   = (const float*)d_in[11];
    const float* w2_root  = (const float*)d_in[12];
    const float* b2       = (const float*)d_in[13];
    const float* cls_w    = (const float*)d_in[14];
    const float* cls_b    = (const float*)d_in[15];
    float* out = (float*)d_out;

    const int nN = in_sizes[0] / 2;
    const int nE = in_sizes[2];
    const int nG = in_sizes[3] - 1;
    const int nb = (nN + SCAN_TILE - 1) / SCAN_TILE;
    const int ntiles = (nN + 63) / 64;
    const int npad = ntiles * 64;

    float *h1, *h2, *h3;
    cudaGetSymbolAddress((void**)&h1, g_h1);
    cudaGetSymbolAddress((void**)&h2, g_h2);
    cudaGetSymbolAddress((void**)&h3, g_h3);

    // smem: W K*72*2 bytes + A 2 bufs * 64*(K+8)*2 bytes
    const int smem1 = 128 * 72 * 2 + 2 * 64 * 136 * 2;   // 18432 + 34816 = 53248
    const int smem2 = 256 * 72 * 2 + 2 * 64 * 264 * 2;   // 36864 + 67584 = 104448
    cudaFuncSetAttribute((const void*)k_gemm_hmma<128>,
                         cudaFuncAttributeMaxDynamicSharedMemorySize, smem1);
    cudaFuncSetAttribute((const void*)k_gemm_hmma<256>,
                         cudaFuncAttributeMaxDynamicSharedMemorySize, smem2);

    // CSR by destination
    k_zero_deg<<<(nN + 255) / 256, 256>>>(nN);
    k_count_deg<<<(nE + 255) / 256, 256>>>(edge_index, nE);
    k_scan_reduce<<<nb, SCAN_T>>>(nN);
    k_scan_mid<<<1, NB_MAX>>>(nb, nN);
    k_scan_final<<<nb, SCAN_T>>>(nN);
    k_fill_adj<<<(nE + 255) / 256, 256>>>(edge_index, edge_type, nE);

    // Feature pipeline
    k_pre<<<(nN * 32 + 255) / 256, 256>>>(x, shape_emb, color_emb, pre_w, pre_b, nN);

    k_agg32<<<(npad + 7) / 8, 256>>>(h1, nN, npad);
    k_gemm_hmma<128><<<NSM * 2, 256, smem1>>>(w1_rel, w1_root, b1, h2, nN);

    k_agg64<<<(npad + 7) / 8, 256>>>(h2, nN, npad);
    k_gemm_hmma<256><<<NSM * 2, 256, smem2>>>(w2_rel, w2_root, b2, h3, nN);

    k_cls<<<(nG * 10 + 255) / 256, 256>>>(ptr, cls_w, cls_b, out, nG);
}